// round 12
// baseline (speedup 1.0000x reference)
#include <cuda_runtime.h>
#include <cuda_bf16.h>
#include <cstdint>

// Problem constants
constexpr int NB = 8;      // batch
constexpr int T  = 1024;   // sequence
constexpr int D  = 512;    // model dim
constexpr int H  = 8;      // heads
constexpr int HD = 64;     // head dim
constexpr int M  = NB * T; // 8192 rows

// ---------------- scratch (device globals; allocation-free at runtime) -------
__device__ float g_xn[M * D];
__device__ float g_qu[M * D];
__device__ float g_qv[M * D];
__device__ float g_k [M * D];
__device__ float g_v [M * D];
__device__ float g_p [M * D];
__device__ float g_ctx[M * D];
__device__ __nv_bfloat16 g_bd[(size_t)NB * H * T * T]; // positional scores (pre-shift, bf16)

// ---------------- helpers ----------------------------------------------------
__device__ __forceinline__ uint32_t f2tf(float f) {
    uint32_t u; asm("cvt.rna.tf32.f32 %0, %1;" : "=r"(u) : "f"(f)); return u;
}
__device__ __forceinline__ void mma8(float* c, const uint32_t* a, const uint32_t* b) {
    asm volatile(
        "mma.sync.aligned.m16n8k8.row.col.f32.tf32.tf32.f32 "
        "{%0,%1,%2,%3}, {%4,%5,%6,%7}, {%8,%9}, {%0,%1,%2,%3};\n"
        : "+f"(c[0]), "+f"(c[1]), "+f"(c[2]), "+f"(c[3])
        : "r"(a[0]), "r"(a[1]), "r"(a[2]), "r"(a[3]), "r"(b[0]), "r"(b[1]));
}
__device__ __forceinline__ void mma16bf(float* c, const uint32_t* a, const uint32_t* b) {
    asm volatile(
        "mma.sync.aligned.m16n8k16.row.col.f32.bf16.bf16.f32 "
        "{%0,%1,%2,%3}, {%4,%5,%6,%7}, {%8,%9}, {%0,%1,%2,%3};\n"
        : "+f"(c[0]), "+f"(c[1]), "+f"(c[2]), "+f"(c[3])
        : "r"(a[0]), "r"(a[1]), "r"(a[2]), "r"(a[3]), "r"(b[0]), "r"(b[1]));
}
__device__ __forceinline__ void cpa16(uint32_t dst, const void* src) {
    asm volatile("cp.async.cg.shared.global [%0], [%1], 16;" :: "r"(dst), "l"(src));
}

// rel_shift lookup: shift[i][j] per Transformer-XL semantics (bf16 source)
__device__ __forceinline__ float shift_val(const __nv_bfloat16* __restrict__ BDb, int i, int j) {
    if (j <= i)      return __bfloat162float(BDb[(size_t)i * T + (j - i + T - 1)]);
    if (j == i + 1)  return 0.f;
    return __bfloat162float(BDb[(size_t)(i + 1) * T + (j - i - 2)]);
}

// ---------------- LayerNorm --------------------------------------------------
__global__ void ln_kernel(const float* __restrict__ x,
                          const float* __restrict__ gamma,
                          const float* __restrict__ beta,
                          float* __restrict__ out) {
    int row = blockIdx.x;
    int t = threadIdx.x; // 128 threads
    const float4* xr = reinterpret_cast<const float4*>(x + (size_t)row * D);
    float4 v = xr[t];
    float s = v.x + v.y + v.z + v.w;
    __shared__ float red[4], red2[4];
    #pragma unroll
    for (int o = 16; o > 0; o >>= 1) s += __shfl_xor_sync(0xffffffffu, s, o);
    if ((t & 31) == 0) red[t >> 5] = s;
    __syncthreads();
    float mu = (red[0] + red[1] + red[2] + red[3]) * (1.0f / D);
    float dx = v.x - mu, dy = v.y - mu, dz = v.z - mu, dw = v.w - mu;
    float ss = dx * dx + dy * dy + dz * dz + dw * dw;
    #pragma unroll
    for (int o = 16; o > 0; o >>= 1) ss += __shfl_xor_sync(0xffffffffu, ss, o);
    if ((t & 31) == 0) red2[t >> 5] = ss;
    __syncthreads();
    float var = (red2[0] + red2[1] + red2[2] + red2[3]) * (1.0f / D);
    float rstd = rsqrtf(var + 1e-3f);
    const float4* g4 = reinterpret_cast<const float4*>(gamma);
    const float4* b4 = reinterpret_cast<const float4*>(beta);
    float4 g = g4[t], b = b4[t];
    float4 o4;
    o4.x = dx * rstd * g.x + b.x;
    o4.y = dy * rstd * g.y + b.y;
    o4.z = dz * rstd * g.z + b.z;
    o4.w = dw * rstd * g.w + b.w;
    reinterpret_cast<float4*>(out + (size_t)row * D)[t] = o4;
}

// ------- tf32 SGEMM, cp.async 3-stage ring, one sync per k-tile --------------
constexpr int SG_A = 128 * 36;  // u32 per A stage
constexpr int SG_B = 32 * 136;  // u32 per B stage
constexpr int SG_ST = SG_A + SG_B;
constexpr int SGEMM_SMEM_U32 = 3 * SG_ST; // 26880 u32 = 107520 B

__global__ void __launch_bounds__(256, 2) sgemm512_tf32(
    const float* __restrict__ A, const float* __restrict__ W,
    const float* __restrict__ bias, const float* __restrict__ biasU,
    const float* __restrict__ resid, float* __restrict__ out1,
    const float* __restrict__ biasV, float* __restrict__ out2) {
    extern __shared__ uint32_t sg4[];
    int t = threadIdx.x;
    int bm = blockIdx.y * 128, bn = blockIdx.x * 128;
    int wid = t >> 5, lane = t & 31;
    int wm = wid & 3, wn = wid >> 2;
    int g = lane >> 2, q4 = lane & 3;
    uint32_t sbase = (uint32_t)__cvta_generic_to_shared(sg4);

    float acc[2][8][4];
    #pragma unroll
    for (int i = 0; i < 2; i++)
        #pragma unroll
        for (int j = 0; j < 8; j++)
            #pragma unroll
            for (int k = 0; k < 4; k++) acc[i][j][k] = 0.f;

    auto load_stage = [&](int st, int k0) {
        #pragma unroll
        for (int p = 0; p < 4; p++) {
            int chunk = t + p * 256;
            int row = chunk >> 3, c4 = (chunk & 7) * 4;
            uint32_t dst = sbase + (uint32_t)(st * SG_ST + row * 36 + c4) * 4u;
            cpa16(dst, A + (size_t)(bm + row) * D + k0 + c4);
        }
        #pragma unroll
        for (int p = 0; p < 4; p++) {
            int chunk = t + p * 256;
            int row = chunk >> 5, c4 = (chunk & 31) * 4;
            uint32_t dst = sbase + (uint32_t)(st * SG_ST + SG_A + row * 136 + c4) * 4u;
            cpa16(dst, W + (size_t)(k0 + row) * D + bn + c4);
        }
        asm volatile("cp.async.commit_group;");
    };

    load_stage(0, 0);
    load_stage(1, 32);

    int stage = 0;
    for (int kt = 0; kt < 16; kt++) {
        if (kt == 15) { asm volatile("cp.async.wait_group 0;"); }
        else          { asm volatile("cp.async.wait_group 1;"); }
        __syncthreads(); // tile kt ready for all; iteration kt-1 MMAs done everywhere
        if (kt + 2 < 16) load_stage((stage + 2) % 3, (kt + 2) * 32);

        const uint32_t* Asb = sg4 + stage * SG_ST;
        const uint32_t* Bsb = sg4 + stage * SG_ST + SG_A;
        #pragma unroll
        for (int kc = 0; kc < 4; kc++) {
            int kb = kc * 8;
            uint32_t af[2][4];
            #pragma unroll
            for (int mt = 0; mt < 2; mt++) {
                int r = wm * 32 + mt * 16 + g;
                af[mt][0] = Asb[r * 36 + kb + q4];
                af[mt][1] = Asb[(r + 8) * 36 + kb + q4];
                af[mt][2] = Asb[r * 36 + kb + q4 + 4];
                af[mt][3] = Asb[(r + 8) * 36 + kb + q4 + 4];
            }
            #pragma unroll
            for (int nt = 0; nt < 8; nt++) {
                int c = wn * 64 + nt * 8 + g;
                uint32_t bf[2];
                bf[0] = Bsb[(kb + q4) * 136 + c];
                bf[1] = Bsb[(kb + q4 + 4) * 136 + c];
                mma8(acc[0][nt], af[0], bf);
                mma8(acc[1][nt], af[1], bf);
            }
        }
        stage = (stage + 1) % 3;
    }

    #pragma unroll
    for (int mt = 0; mt < 2; mt++) {
        int r0 = bm + wm * 32 + mt * 16 + g;
        #pragma unroll
        for (int nt = 0; nt < 8; nt++) {
            int c0 = bn + wn * 64 + nt * 8 + q4 * 2;
            #pragma unroll
            for (int rr = 0; rr < 2; rr++) {
                int r = r0 + rr * 8;
                float b0 = acc[mt][nt][rr * 2 + 0];
                float b1 = acc[mt][nt][rr * 2 + 1];
                if (bias) { b0 += bias[c0]; b1 += bias[c0 + 1]; }
                float v0 = b0, v1 = b1;
                if (biasU) { v0 += biasU[c0]; v1 += biasU[c0 + 1]; }
                if (resid) {
                    float2 rv = *reinterpret_cast<const float2*>(resid + (size_t)r * D + c0);
                    v0 += rv.x; v1 += rv.y;
                }
                *reinterpret_cast<float2*>(out1 + (size_t)r * D + c0) = make_float2(v0, v1);
                if (out2) {
                    float w0 = b0 + biasV[c0], w1 = b1 + biasV[c0 + 1];
                    *reinterpret_cast<float2*>(out2 + (size_t)r * D + c0) = make_float2(w0, w1);
                }
            }
        }
    }
}

// ---------------- tf32 score GEMM (for BD, bf16 out) -------------------------
__global__ void __launch_bounds__(256) score_tf32(
    const float* __restrict__ Qx, const float* __restrict__ Kx,
    __nv_bfloat16* __restrict__ S) {
    extern __shared__ uint32_t sm4[];
    uint32_t (*Qs)[68] = reinterpret_cast<uint32_t(*)[68]>(sm4);
    uint32_t (*Ks)[68] = reinterpret_cast<uint32_t(*)[68]>(sm4 + 128 * 68);
    int bh = blockIdx.y;
    int b = bh >> 3, h = bh & 7;
    int i0 = blockIdx.x * 128;
    const float* Qb = Qx + (size_t)b * T * D + h * HD;
    const float* Kb = Kx + (size_t)b * T * D + h * HD;
    int t = threadIdx.x, wid = t >> 5, lane = t & 31;
    int wm = wid & 3, wn = wid >> 2;
    int g = lane >> 2, q4 = lane & 3;
    int lrow = t >> 4, lc4 = (t & 15) * 4;

    #pragma unroll
    for (int p = 0; p < 8; p++) {
        int r = lrow + p * 16;
        float4 v = *reinterpret_cast<const float4*>(Qb + (size_t)(i0 + r) * D + lc4);
        Qs[r][lc4 + 0] = f2tf(v.x); Qs[r][lc4 + 1] = f2tf(v.y);
        Qs[r][lc4 + 2] = f2tf(v.z); Qs[r][lc4 + 3] = f2tf(v.w);
    }

    for (int j0 = 0; j0 < T; j0 += 128) {
        __syncthreads();
        #pragma unroll
        for (int p = 0; p < 8; p++) {
            int r = lrow + p * 16;
            float4 v = *reinterpret_cast<const float4*>(Kb + (size_t)(j0 + r) * D + lc4);
            Ks[r][lc4 + 0] = f2tf(v.x); Ks[r][lc4 + 1] = f2tf(v.y);
            Ks[r][lc4 + 2] = f2tf(v.z); Ks[r][lc4 + 3] = f2tf(v.w);
        }
        __syncthreads();

        float acc[2][8][4];
        #pragma unroll
        for (int i = 0; i < 2; i++)
            #pragma unroll
            for (int j = 0; j < 8; j++)
                #pragma unroll
                for (int k = 0; k < 4; k++) acc[i][j][k] = 0.f;

        #pragma unroll
        for (int kc = 0; kc < 8; kc++) {
            int kb = kc * 8;
            uint32_t af[2][4];
            #pragma unroll
            for (int mt = 0; mt < 2; mt++) {
                int r = wm * 32 + mt * 16 + g;
                af[mt][0] = Qs[r][kb + q4];      af[mt][1] = Qs[r + 8][kb + q4];
                af[mt][2] = Qs[r][kb + q4 + 4];  af[mt][3] = Qs[r + 8][kb + q4 + 4];
            }
            #pragma unroll
            for (int nt = 0; nt < 8; nt++) {
                int c = wn * 64 + nt * 8 + g;
                uint32_t bf[2];
                bf[0] = Ks[c][kb + q4]; bf[1] = Ks[c][kb + q4 + 4];
                mma8(acc[0][nt], af[0], bf);
                mma8(acc[1][nt], af[1], bf);
            }
        }

        #pragma unroll
        for (int mt = 0; mt < 2; mt++) {
            int r0 = i0 + wm * 32 + mt * 16 + g;
            #pragma unroll
            for (int nt = 0; nt < 8; nt++) {
                int c0 = j0 + wn * 64 + nt * 8 + q4 * 2;
                size_t base = ((size_t)bh * T + r0) * T + c0;
                *reinterpret_cast<__nv_bfloat162*>(S + base) =
                    __floats2bfloat162_rn(acc[mt][nt][0], acc[mt][nt][1]);
                *reinterpret_cast<__nv_bfloat162*>(S + base + (size_t)8 * T) =
                    __floats2bfloat162_rn(acc[mt][nt][2], acc[mt][nt][3]);
            }
        }
    }
}

// ======= fused: content score + shift + exp + P@V + normalize -> ctx =========
constexpr int FQ_OFF = 0;                    // Qs[128][68] tf32
constexpr int FU_OFF = FQ_OFF + 128 * 68;    // union: Ks[64][68] tf32 | Ps[128][36] bf16x2
constexpr int FV_OFF = FU_OFF + 128 * 36;    // Vs[64][36] bf16x2 (V^T pairs)
constexpr int FR_OFF = FV_OFF + 64 * 36;     // redS[2][128] floats
constexpr int FUSED_SMEM_U32 = FR_OFF + 256;

__global__ void __launch_bounds__(256) fused_softmax_av(
    const float* __restrict__ Qx, const float* __restrict__ Kx,
    const float* __restrict__ Vx, const __nv_bfloat16* __restrict__ BD,
    float* __restrict__ ctx) {
    extern __shared__ uint32_t sm4[];
    uint32_t (*Qs)[68] = reinterpret_cast<uint32_t(*)[68]>(sm4 + FQ_OFF);
    uint32_t (*Ks)[68] = reinterpret_cast<uint32_t(*)[68]>(sm4 + FU_OFF);
    uint32_t (*Ps)[36] = reinterpret_cast<uint32_t(*)[36]>(sm4 + FU_OFF);
    uint32_t (*Vs)[36] = reinterpret_cast<uint32_t(*)[36]>(sm4 + FV_OFF);
    float* redS = reinterpret_cast<float*>(sm4 + FR_OFF);

    int bh = blockIdx.y;
    int b = bh >> 3, h = bh & 7;
    int i0 = blockIdx.x * 128;
    const float* Qb = Qx + (size_t)b * T * D + h * HD;
    const float* Kb = Kx + (size_t)b * T * D + h * HD;
    const float* Vb = Vx + (size_t)b * T * D + h * HD;
    const __nv_bfloat16* BDb = BD + (size_t)bh * T * T;

    int t = threadIdx.x, wid = t >> 5, lane = t & 31;
    int wm = wid & 3, wn = wid >> 2;
    int g = lane >> 2, q4 = lane & 3;

    // stage Q tile (128 x 64) as tf32
    {
        int lrow = t >> 1, lc0 = (t & 1) * 32;
        #pragma unroll
        for (int p = 0; p < 4; p++) {
            int c = lc0 + p * 8;
            float4 v = *reinterpret_cast<const float4*>(Qb + (size_t)(i0 + lrow) * D + c);
            Qs[lrow][c + 0] = f2tf(v.x); Qs[lrow][c + 1] = f2tf(v.y);
            Qs[lrow][c + 2] = f2tf(v.z); Qs[lrow][c + 3] = f2tf(v.w);
            float4 v2 = *reinterpret_cast<const float4*>(Qb + (size_t)(i0 + lrow) * D + c + 4);
            Qs[lrow][c + 4] = f2tf(v2.x); Qs[lrow][c + 5] = f2tf(v2.y);
            Qs[lrow][c + 6] = f2tf(v2.z); Qs[lrow][c + 7] = f2tf(v2.w);
        }
    }

    float rs[2][2] = {{0.f, 0.f}, {0.f, 0.f}};
    float o_acc[2][4][4];
    #pragma unroll
    for (int i = 0; i < 2; i++)
        #pragma unroll
        for (int j = 0; j < 4; j++)
            #pragma unroll
            for (int k = 0; k < 4; k++) o_acc[i][j][k] = 0.f;

    int krow = t >> 2, kc4 = (t & 3) * 4;
    int vcol = t & 63, vg = t >> 6;

    for (int j0 = 0; j0 < T; j0 += 64) {
        __syncthreads();

        #pragma unroll
        for (int p = 0; p < 4; p++) {
            int c = kc4 + p * 16;
            float4 kv = *reinterpret_cast<const float4*>(Kb + (size_t)(j0 + krow) * D + c);
            Ks[krow][c + 0] = f2tf(kv.x); Ks[krow][c + 1] = f2tf(kv.y);
            Ks[krow][c + 2] = f2tf(kv.z); Ks[krow][c + 3] = f2tf(kv.w);
        }
        {
            uint32_t prs[8];
            #pragma unroll
            for (int kk = 0; kk < 8; kk++) {
                int kp = vg * 8 + kk;
                float lo = Vb[(size_t)(j0 + 2 * kp) * D + vcol];
                float hi = Vb[(size_t)(j0 + 2 * kp + 1) * D + vcol];
                __nv_bfloat162 pr = __floats2bfloat162_rn(lo, hi);
                prs[kk] = *reinterpret_cast<uint32_t*>(&pr);
            }
            *reinterpret_cast<uint4*>(&Vs[vcol][vg * 8 + 0]) =
                make_uint4(prs[0], prs[1], prs[2], prs[3]);
            *reinterpret_cast<uint4*>(&Vs[vcol][vg * 8 + 4]) =
                make_uint4(prs[4], prs[5], prs[6], prs[7]);
        }
        __syncthreads();

        float acc[2][4][4];
        #pragma unroll
        for (int i = 0; i < 2; i++)
            #pragma unroll
            for (int j = 0; j < 4; j++)
                #pragma unroll
                for (int k = 0; k < 4; k++) acc[i][j][k] = 0.f;
        #pragma unroll
        for (int kc = 0; kc < 8; kc++) {
            int kb = kc * 8;
            uint32_t af[2][4];
            #pragma unroll
            for (int mt = 0; mt < 2; mt++) {
                int r = wm * 32 + mt * 16 + g;
                af[mt][0] = Qs[r][kb + q4];      af[mt][1] = Qs[r + 8][kb + q4];
                af[mt][2] = Qs[r][kb + q4 + 4];  af[mt][3] = Qs[r + 8][kb + q4 + 4];
            }
            #pragma unroll
            for (int nt = 0; nt < 4; nt++) {
                int c = wn * 32 + nt * 8 + g;
                uint32_t bf[2];
                bf[0] = Ks[c][kb + q4]; bf[1] = Ks[c][kb + q4 + 4];
                mma8(acc[0][nt], af[0], bf);
                mma8(acc[1][nt], af[1], bf);
            }
        }
        __syncthreads();

        #pragma unroll
        for (int mt = 0; mt < 2; mt++) {
            #pragma unroll
            for (int nt = 0; nt < 4; nt++) {
                int cl = wn * 32 + nt * 8 + q4 * 2;
                #pragma unroll
                for (int rr = 0; rr < 2; rr++) {
                    int rl = wm * 32 + mt * 16 + g + rr * 8;
                    int i = i0 + rl, j = j0 + cl;
                    float sh0 = shift_val(BDb, i, j);
                    float sh1 = shift_val(BDb, i, j + 1);
                    float e0 = __expf((acc[mt][nt][rr * 2 + 0] + sh0) * 0.125f);
                    float e1 = __expf((acc[mt][nt][rr * 2 + 1] + sh1) * 0.125f);
                    rs[mt][rr] += e0 + e1;
                    __nv_bfloat162 pr = __floats2bfloat162_rn(e0, e1);
                    Ps[rl][cl >> 1] = *reinterpret_cast<uint32_t*>(&pr);
                }
            }
        }
        __syncthreads();

        #pragma unroll
        for (int kc = 0; kc < 4; kc++) {
            int kb = kc * 8;
            uint32_t af[2][4];
            #pragma unroll
            for (int mt = 0; mt < 2; mt++) {
                int r = wm * 32 + mt * 16 + g;
                af[mt][0] = Ps[r][kb + q4];      af[mt][1] = Ps[r + 8][kb + q4];
                af[mt][2] = Ps[r][kb + q4 + 4];  af[mt][3] = Ps[r + 8][kb + q4 + 4];
            }
            #pragma unroll
            for (int nt = 0; nt < 4; nt++) {
                int c = wn * 32 + nt * 8 + g;
                uint32_t bf[2];
                bf[0] = Vs[c][kb + q4]; bf[1] = Vs[c][kb + q4 + 4];
                mma16bf(o_acc[0][nt], af[0], bf);
                mma16bf(o_acc[1][nt], af[1], bf);
            }
        }
    }

    #pragma unroll
    for (int mt = 0; mt < 2; mt++) {
        #pragma unroll
        for (int rr = 0; rr < 2; rr++) {
            float s = rs[mt][rr];
            s += __shfl_xor_sync(0xffffffffu, s, 1);
            s += __shfl_xor_sync(0xffffffffu, s, 2);
            int r = wm * 32 + mt * 16 + g + rr * 8;
            if (q4 == 0) redS[wn * 128 + r] = s;
        }
    }
    __syncthreads();

    float* Cg = ctx + ((size_t)(b * T + i0)) * D + h * HD;
    #pragma unroll
    for (int mt = 0; mt < 2; mt++) {
        #pragma unroll
        for (int rr = 0; rr < 2; rr++) {
            int r = wm * 32 + mt * 16 + g + rr * 8;
            float inv = 1.0f / (redS[r] + redS[128 + r]);
            #pragma unroll
            for (int nt = 0; nt < 4; nt++) {
                int c = wn * 32 + nt * 8 + q4 * 2;
                *reinterpret_cast<float2*>(Cg + (size_t)r * D + c) =
                    make_float2(o_acc[mt][nt][rr * 2 + 0] * inv,
                                o_acc[mt][nt][rr * 2 + 1] * inv);
            }
        }
    }
}

// ---------------- launch -----------------------------------------------------
extern "C" void kernel_launch(void* const* d_in, const int* in_sizes, int n_in,
                              void* d_out, int out_size) {
    const float* inputs = (const float*)d_in[0];
    const float* pos    = (const float*)d_in[1];
    const float* gamma  = (const float*)d_in[2];
    const float* beta   = (const float*)d_in[3];
    const float* wq     = (const float*)d_in[4];
    const float* bq     = (const float*)d_in[5];
    const float* wk     = (const float*)d_in[6];
    const float* bk     = (const float*)d_in[7];
    const float* wv     = (const float*)d_in[8];
    const float* bv     = (const float*)d_in[9];
    const float* wpos   = (const float*)d_in[10];
    const float* u      = (const float*)d_in[11];
    const float* vb     = (const float*)d_in[12];
    const float* wo     = (const float*)d_in[13];
    const float* bo     = (const float*)d_in[14];
    float* out = (float*)d_out;

    float *xn, *qu, *qv, *kx, *vx, *px, *ctx;
    __nv_bfloat16 *bd;
    cudaGetSymbolAddress((void**)&xn,  g_xn);
    cudaGetSymbolAddress((void**)&qu,  g_qu);
    cudaGetSymbolAddress((void**)&qv,  g_qv);
    cudaGetSymbolAddress((void**)&kx,  g_k);
    cudaGetSymbolAddress((void**)&vx,  g_v);
    cudaGetSymbolAddress((void**)&px,  g_p);
    cudaGetSymbolAddress((void**)&ctx, g_ctx);
    cudaGetSymbolAddress((void**)&bd,  g_bd);

    const int SGEMM_SMEM = SGEMM_SMEM_U32 * 4; // 107520
    const int SCORE_SMEM = 2 * 128 * 68 * 4;
    const int FUSED_SMEM = FUSED_SMEM_U32 * 4;
    cudaFuncSetAttribute(sgemm512_tf32, cudaFuncAttributeMaxDynamicSharedMemorySize, SGEMM_SMEM);
    cudaFuncSetAttribute(score_tf32, cudaFuncAttributeMaxDynamicSharedMemorySize, SCORE_SMEM);
    cudaFuncSetAttribute(fused_softmax_av, cudaFuncAttributeMaxDynamicSharedMemorySize, FUSED_SMEM);

    // 1. LayerNorm
    ln_kernel<<<M, 128>>>(inputs, gamma, beta, xn);

    // 2. Projections (tf32 MMA, 3-stage cp.async)
    dim3 gg(4, 64);
    sgemm512_tf32<<<gg, 256, SGEMM_SMEM>>>(xn,  wq,   bq,      u,       nullptr, qu, vb, qv);
    sgemm512_tf32<<<gg, 256, SGEMM_SMEM>>>(xn,  wk,   bk,      nullptr, nullptr, kx, nullptr, nullptr);
    sgemm512_tf32<<<gg, 256, SGEMM_SMEM>>>(xn,  wv,   bv,      nullptr, nullptr, vx, nullptr, nullptr);
    sgemm512_tf32<<<gg, 256, SGEMM_SMEM>>>(pos, wpos, nullptr, nullptr, nullptr, px, nullptr, nullptr);

    // 3. BD = (Qv) @ P^T (pre-shift positional scores, bf16)
    dim3 sg(8, NB * H);
    score_tf32<<<sg, 256, SCORE_SMEM>>>(qv, px, bd);

    // 4. fused content score + shift + exp + P@V + normalize -> ctx
    fused_softmax_av<<<dim3(8, NB * H), 256, FUSED_SMEM>>>(qu, kx, vx, bd, ctx);

    // 5. output projection + bias + residual
    sgemm512_tf32<<<gg, 256, SGEMM_SMEM>>>(ctx, wo, bo, nullptr, inputs, out, nullptr, nullptr);
}

// round 15
// speedup vs baseline: 1.1791x; 1.1791x over previous
#include <cuda_runtime.h>
#include <cuda_bf16.h>
#include <cstdint>

// Problem constants
constexpr int NB = 8;      // batch
constexpr int T  = 1024;   // sequence
constexpr int D  = 512;    // model dim
constexpr int H  = 8;      // heads
constexpr int HD = 64;     // head dim
constexpr int M  = NB * T; // 8192 rows

// ---------------- scratch (device globals; allocation-free at runtime) -------
__device__ float g_xn[M * D];
__device__ float g_qu[M * D];
__device__ float g_qv[M * D];
__device__ float g_k [M * D];
__device__ float g_v [M * D];
__device__ float g_p [M * D];
__device__ float g_ctx[M * D];
__device__ float g_bd[(size_t)NB * H * T * T]; // pre-shift pos scores (fp32)

// ---------------- helpers ----------------------------------------------------
__device__ __forceinline__ uint32_t f2tf(float f) {
    uint32_t u; asm("cvt.rna.tf32.f32 %0, %1;" : "=r"(u) : "f"(f)); return u;
}
__device__ __forceinline__ void mma8(float* c, const uint32_t* a, const uint32_t* b) {
    asm volatile(
        "mma.sync.aligned.m16n8k8.row.col.f32.tf32.tf32.f32 "
        "{%0,%1,%2,%3}, {%4,%5,%6,%7}, {%8,%9}, {%0,%1,%2,%3};\n"
        : "+f"(c[0]), "+f"(c[1]), "+f"(c[2]), "+f"(c[3])
        : "r"(a[0]), "r"(a[1]), "r"(a[2]), "r"(a[3]), "r"(b[0]), "r"(b[1]));
}
__device__ __forceinline__ void mma16bf(float* c, const uint32_t* a, const uint32_t* b) {
    asm volatile(
        "mma.sync.aligned.m16n8k16.row.col.f32.bf16.bf16.f32 "
        "{%0,%1,%2,%3}, {%4,%5,%6,%7}, {%8,%9}, {%0,%1,%2,%3};\n"
        : "+f"(c[0]), "+f"(c[1]), "+f"(c[2]), "+f"(c[3])
        : "r"(a[0]), "r"(a[1]), "r"(a[2]), "r"(a[3]), "r"(b[0]), "r"(b[1]));
}
__device__ __forceinline__ void cpa16(uint32_t dst, const void* src) {
    asm volatile("cp.async.cg.shared.global [%0], [%1], 16;" :: "r"(dst), "l"(src));
}

// rel_shift lookup (fp32 source)
__device__ __forceinline__ float shift_val(const float* __restrict__ BDb, int i, int j) {
    if (j <= i)      return BDb[(size_t)i * T + (j - i + T - 1)];
    if (j == i + 1)  return 0.f;
    return BDb[(size_t)(i + 1) * T + (j - i - 2)];
}

// ---------------- LayerNorm --------------------------------------------------
__global__ void ln_kernel(const float* __restrict__ x,
                          const float* __restrict__ gamma,
                          const float* __restrict__ beta,
                          float* __restrict__ out) {
    int row = blockIdx.x;
    int t = threadIdx.x; // 128 threads
    const float4* xr = reinterpret_cast<const float4*>(x + (size_t)row * D);
    float4 v = xr[t];
    float s = v.x + v.y + v.z + v.w;
    __shared__ float red[4], red2[4];
    #pragma unroll
    for (int o = 16; o > 0; o >>= 1) s += __shfl_xor_sync(0xffffffffu, s, o);
    if ((t & 31) == 0) red[t >> 5] = s;
    __syncthreads();
    float mu = (red[0] + red[1] + red[2] + red[3]) * (1.0f / D);
    float dx = v.x - mu, dy = v.y - mu, dz = v.z - mu, dw = v.w - mu;
    float ss = dx * dx + dy * dy + dz * dz + dw * dw;
    #pragma unroll
    for (int o = 16; o > 0; o >>= 1) ss += __shfl_xor_sync(0xffffffffu, ss, o);
    if ((t & 31) == 0) red2[t >> 5] = ss;
    __syncthreads();
    float var = (red2[0] + red2[1] + red2[2] + red2[3]) * (1.0f / D);
    float rstd = rsqrtf(var + 1e-3f);
    const float4* g4 = reinterpret_cast<const float4*>(gamma);
    const float4* b4 = reinterpret_cast<const float4*>(beta);
    float4 g = g4[t], b = b4[t];
    float4 o4;
    o4.x = dx * rstd * g.x + b.x;
    o4.y = dy * rstd * g.y + b.y;
    o4.z = dz * rstd * g.z + b.z;
    o4.w = dw * rstd * g.w + b.w;
    reinterpret_cast<float4*>(out + (size_t)row * D)[t] = o4;
}

// ------- tf32 SGEMM, cp.async 2-stage pipeline (R10 proven) ------------------
constexpr int SG_A = 128 * 36;
constexpr int SG_B = 32 * 136;
constexpr int SGEMM_SMEM_U32 = 2 * SG_A + 2 * SG_B; // 71680 B

__global__ void __launch_bounds__(256, 2) sgemm512_tf32(
    const float* __restrict__ A, const float* __restrict__ W,
    const float* __restrict__ bias, const float* __restrict__ biasU,
    const float* __restrict__ resid, float* __restrict__ out1,
    const float* __restrict__ biasV, float* __restrict__ out2) {
    extern __shared__ uint32_t sg4[];
    int t = threadIdx.x;
    int bm = blockIdx.y * 128, bn = blockIdx.x * 128;
    int wid = t >> 5, lane = t & 31;
    int wm = wid & 3, wn = wid >> 2;
    int g = lane >> 2, q4 = lane & 3;
    uint32_t sbase = (uint32_t)__cvta_generic_to_shared(sg4);

    float acc[2][8][4];
    #pragma unroll
    for (int i = 0; i < 2; i++)
        #pragma unroll
        for (int j = 0; j < 8; j++)
            #pragma unroll
            for (int k = 0; k < 4; k++) acc[i][j][k] = 0.f;

    auto load_stage = [&](int st, int k0) {
        #pragma unroll
        for (int p = 0; p < 4; p++) {
            int chunk = t + p * 256;
            int row = chunk >> 3, c4 = (chunk & 7) * 4;
            uint32_t dst = sbase + (uint32_t)(st * SG_A + row * 36 + c4) * 4u;
            cpa16(dst, A + (size_t)(bm + row) * D + k0 + c4);
        }
        #pragma unroll
        for (int p = 0; p < 4; p++) {
            int chunk = t + p * 256;
            int row = chunk >> 5, c4 = (chunk & 31) * 4;
            uint32_t dst = sbase + (uint32_t)(2 * SG_A + st * SG_B + row * 136 + c4) * 4u;
            cpa16(dst, W + (size_t)(k0 + row) * D + bn + c4);
        }
        asm volatile("cp.async.commit_group;");
    };

    load_stage(0, 0);

    for (int kt = 0; kt < 16; kt++) {
        __syncthreads();
        if (kt + 1 < 16) {
            load_stage((kt + 1) & 1, (kt + 1) * 32);
            asm volatile("cp.async.wait_group 1;");
        } else {
            asm volatile("cp.async.wait_group 0;");
        }
        __syncthreads();

        const uint32_t* Asb = sg4 + (kt & 1) * SG_A;
        const uint32_t* Bsb = sg4 + 2 * SG_A + (kt & 1) * SG_B;
        #pragma unroll
        for (int kc = 0; kc < 4; kc++) {
            int kb = kc * 8;
            uint32_t af[2][4];
            #pragma unroll
            for (int mt = 0; mt < 2; mt++) {
                int r = wm * 32 + mt * 16 + g;
                af[mt][0] = Asb[r * 36 + kb + q4];
                af[mt][1] = Asb[(r + 8) * 36 + kb + q4];
                af[mt][2] = Asb[r * 36 + kb + q4 + 4];
                af[mt][3] = Asb[(r + 8) * 36 + kb + q4 + 4];
            }
            #pragma unroll
            for (int nt = 0; nt < 8; nt++) {
                int c = wn * 64 + nt * 8 + g;
                uint32_t bf[2];
                bf[0] = Bsb[(kb + q4) * 136 + c];
                bf[1] = Bsb[(kb + q4 + 4) * 136 + c];
                mma8(acc[0][nt], af[0], bf);
                mma8(acc[1][nt], af[1], bf);
            }
        }
    }

    #pragma unroll
    for (int mt = 0; mt < 2; mt++) {
        int r0 = bm + wm * 32 + mt * 16 + g;
        #pragma unroll
        for (int nt = 0; nt < 8; nt++) {
            int c0 = bn + wn * 64 + nt * 8 + q4 * 2;
            #pragma unroll
            for (int rr = 0; rr < 2; rr++) {
                int r = r0 + rr * 8;
                float b0 = acc[mt][nt][rr * 2 + 0];
                float b1 = acc[mt][nt][rr * 2 + 1];
                if (bias) { b0 += bias[c0]; b1 += bias[c0 + 1]; }
                float v0 = b0, v1 = b1;
                if (biasU) { v0 += biasU[c0]; v1 += biasU[c0 + 1]; }
                if (resid) {
                    float2 rv = *reinterpret_cast<const float2*>(resid + (size_t)r * D + c0);
                    v0 += rv.x; v1 += rv.y;
                }
                *reinterpret_cast<float2*>(out1 + (size_t)r * D + c0) = make_float2(v0, v1);
                if (out2) {
                    float w0 = b0 + biasV[c0], w1 = b1 + biasV[c0 + 1];
                    *reinterpret_cast<float2*>(out2 + (size_t)r * D + c0) = make_float2(w0, w1);
                }
            }
        }
    }
}

// ---------------- tf32 score GEMM (for BD, fp32 out) -------------------------
__global__ void __launch_bounds__(256) score_tf32(
    const float* __restrict__ Qx, const float* __restrict__ Kx, float* __restrict__ S) {
    extern __shared__ uint32_t sm4[];
    uint32_t (*Qs)[68] = reinterpret_cast<uint32_t(*)[68]>(sm4);
    uint32_t (*Ks)[68] = reinterpret_cast<uint32_t(*)[68]>(sm4 + 128 * 68);
    int bh = blockIdx.y;
    int b = bh >> 3, h = bh & 7;
    int i0 = blockIdx.x * 128;
    const float* Qb = Qx + (size_t)b * T * D + h * HD;
    const float* Kb = Kx + (size_t)b * T * D + h * HD;
    int t = threadIdx.x, wid = t >> 5, lane = t & 31;
    int wm = wid & 3, wn = wid >> 2;
    int g = lane >> 2, q4 = lane & 3;
    int lrow = t >> 4, lc4 = (t & 15) * 4;

    #pragma unroll
    for (int p = 0; p < 8; p++) {
        int r = lrow + p * 16;
        float4 v = *reinterpret_cast<const float4*>(Qb + (size_t)(i0 + r) * D + lc4);
        Qs[r][lc4 + 0] = f2tf(v.x); Qs[r][lc4 + 1] = f2tf(v.y);
        Qs[r][lc4 + 2] = f2tf(v.z); Qs[r][lc4 + 3] = f2tf(v.w);
    }

    for (int j0 = 0; j0 < T; j0 += 128) {
        __syncthreads();
        #pragma unroll
        for (int p = 0; p < 8; p++) {
            int r = lrow + p * 16;
            float4 v = *reinterpret_cast<const float4*>(Kb + (size_t)(j0 + r) * D + lc4);
            Ks[r][lc4 + 0] = f2tf(v.x); Ks[r][lc4 + 1] = f2tf(v.y);
            Ks[r][lc4 + 2] = f2tf(v.z); Ks[r][lc4 + 3] = f2tf(v.w);
        }
        __syncthreads();

        float acc[2][8][4];
        #pragma unroll
        for (int i = 0; i < 2; i++)
            #pragma unroll
            for (int j = 0; j < 8; j++)
                #pragma unroll
                for (int k = 0; k < 4; k++) acc[i][j][k] = 0.f;

        #pragma unroll
        for (int kc = 0; kc < 8; kc++) {
            int kb = kc * 8;
            uint32_t af[2][4];
            #pragma unroll
            for (int mt = 0; mt < 2; mt++) {
                int r = wm * 32 + mt * 16 + g;
                af[mt][0] = Qs[r][kb + q4];      af[mt][1] = Qs[r + 8][kb + q4];
                af[mt][2] = Qs[r][kb + q4 + 4];  af[mt][3] = Qs[r + 8][kb + q4 + 4];
            }
            #pragma unroll
            for (int nt = 0; nt < 8; nt++) {
                int c = wn * 64 + nt * 8 + g;
                uint32_t bf[2];
                bf[0] = Ks[c][kb + q4]; bf[1] = Ks[c][kb + q4 + 4];
                mma8(acc[0][nt], af[0], bf);
                mma8(acc[1][nt], af[1], bf);
            }
        }

        #pragma unroll
        for (int mt = 0; mt < 2; mt++) {
            int r0 = i0 + wm * 32 + mt * 16 + g;
            #pragma unroll
            for (int nt = 0; nt < 8; nt++) {
                int c0 = j0 + wn * 64 + nt * 8 + q4 * 2;
                size_t base = ((size_t)bh * T + r0) * T + c0;
                *reinterpret_cast<float2*>(S + base) =
                    make_float2(acc[mt][nt][0], acc[mt][nt][1]);
                *reinterpret_cast<float2*>(S + base + (size_t)8 * T) =
                    make_float2(acc[mt][nt][2], acc[mt][nt][3]);
            }
        }
    }
}

// ======= fused v2b: content + shift + exp + P@V; cp.async Q/K; 2 syncs/iter ==
constexpr int FQ_OFF = 0;                      // Qs[128][68] raw fp32 bits
constexpr int FK_OFF = FQ_OFF + 128 * 68;      // Ks: 2 stages x [64][68] raw fp32
constexpr int FK_ST  = 64 * 68;
constexpr int FV_OFF = FK_OFF + 2 * FK_ST;     // Vs[64][36] bf16 pairs (V^T)
constexpr int FP_OFF = FV_OFF + 64 * 36;       // Ps[128][36] bf16 pairs
constexpr int FR_OFF = FP_OFF + 128 * 36;      // redS[2][128]
constexpr int FUSED_SMEM_U32 = FR_OFF + 256;   // 24576 u32 = 98304 B

__global__ void __launch_bounds__(256, 2) fused_softmax_av(
    const float* __restrict__ Qx, const float* __restrict__ Kx,
    const float* __restrict__ Vx, const float* __restrict__ BD,
    float* __restrict__ ctx) {
    extern __shared__ uint32_t sm4[];
    uint32_t (*Qs)[68] = reinterpret_cast<uint32_t(*)[68]>(sm4 + FQ_OFF);
    uint32_t (*Vs)[36] = reinterpret_cast<uint32_t(*)[36]>(sm4 + FV_OFF);
    uint32_t (*Ps)[36] = reinterpret_cast<uint32_t(*)[36]>(sm4 + FP_OFF);
    float* redS = reinterpret_cast<float*>(sm4 + FR_OFF);
    uint32_t sbase = (uint32_t)__cvta_generic_to_shared(sm4);

    int bh = blockIdx.y;
    int b = bh >> 3, h = bh & 7;
    int i0 = blockIdx.x * 128;
    const float* Qb = Qx + (size_t)b * T * D + h * HD;
    const float* Kb = Kx + (size_t)b * T * D + h * HD;
    const float* Vb = Vx + (size_t)b * T * D + h * HD;
    const float* BDb = BD + (size_t)bh * T * T;

    int t = threadIdx.x, wid = t >> 5, lane = t & 31;
    int wm = wid & 3, wn = wid >> 2;
    int g = lane >> 2, q4 = lane & 3;

    auto load_k = [&](int st, int j0) {
        #pragma unroll
        for (int p = 0; p < 4; p++) {
            int chunk = t + p * 256;
            int row = chunk >> 4, c4 = (chunk & 15) * 4;
            uint32_t dst = sbase + (uint32_t)(FK_OFF + st * FK_ST + row * 68 + c4) * 4u;
            cpa16(dst, Kb + (size_t)(j0 + row) * D + c4);
        }
        asm volatile("cp.async.commit_group;");
    };

    // Q tile via cp.async (raw fp32): 2048 chunks, 8/thread; same group as K0
    #pragma unroll
    for (int p = 0; p < 8; p++) {
        int chunk = t + p * 256;
        int row = chunk >> 4, c4 = (chunk & 15) * 4;
        uint32_t dst = sbase + (uint32_t)(FQ_OFF + row * 68 + c4) * 4u;
        cpa16(dst, Qb + (size_t)(i0 + row) * D + c4);
    }
    load_k(0, 0);

    float rs[2][2] = {{0.f, 0.f}, {0.f, 0.f}};
    float o_acc[2][4][4];
    #pragma unroll
    for (int i = 0; i < 2; i++)
        #pragma unroll
        for (int j = 0; j < 4; j++)
            #pragma unroll
            for (int k = 0; k < 4; k++) o_acc[i][j][k] = 0.f;

    int vcol = t & 63, vg = t >> 6; // V loader: feature col, group of 8 j-pairs

    for (int it = 0; it < 16; it++) {
        int j0 = it * 64;
        asm volatile("cp.async.wait_group 0;");
        __syncthreads(); // K stage it resident; prior iter P@V done (Vs/Ps free)

        if (it + 1 < 16) load_k((it + 1) & 1, j0 + 64);

        // issue V loads early (registers); consumed after content MMA
        float vl[8], vh[8];
        #pragma unroll
        for (int kk = 0; kk < 8; kk++) {
            int kp = vg * 8 + kk;
            vl[kk] = Vb[(size_t)(j0 + 2 * kp) * D + vcol];
            vh[kk] = Vb[(size_t)(j0 + 2 * kp + 1) * D + vcol];
        }

        const uint32_t* Ksb = sm4 + FK_OFF + (it & 1) * FK_ST;

        // content MMA: 128 x 64, warp 32x32 (hides V LDG latency)
        float acc[2][4][4];
        #pragma unroll
        for (int i = 0; i < 2; i++)
            #pragma unroll
            for (int j = 0; j < 4; j++)
                #pragma unroll
                for (int k = 0; k < 4; k++) acc[i][j][k] = 0.f;
        #pragma unroll
        for (int kc = 0; kc < 8; kc++) {
            int kb = kc * 8;
            uint32_t af[2][4];
            #pragma unroll
            for (int mt = 0; mt < 2; mt++) {
                int r = wm * 32 + mt * 16 + g;
                af[mt][0] = Qs[r][kb + q4];      af[mt][1] = Qs[r + 8][kb + q4];
                af[mt][2] = Qs[r][kb + q4 + 4];  af[mt][3] = Qs[r + 8][kb + q4 + 4];
            }
            #pragma unroll
            for (int nt = 0; nt < 4; nt++) {
                int c = wn * 32 + nt * 8 + g;
                uint32_t bf[2];
                bf[0] = Ksb[c * 68 + kb + q4]; bf[1] = Ksb[c * 68 + kb + q4 + 4];
                mma8(acc[0][nt], af[0], bf);
                mma8(acc[1][nt], af[1], bf);
            }
        }

        // store V^T pairs (regs arrived during MMA)
        {
            uint32_t prs[8];
            #pragma unroll
            for (int kk = 0; kk < 8; kk++) {
                __nv_bfloat162 pr = __floats2bfloat162_rn(vl[kk], vh[kk]);
                prs[kk] = *reinterpret_cast<uint32_t*>(&pr);
            }
            *reinterpret_cast<uint4*>(&Vs[vcol][vg * 8 + 0]) =
                make_uint4(prs[0], prs[1], prs[2], prs[3]);
            *reinterpret_cast<uint4*>(&Vs[vcol][vg * 8 + 4]) =
                make_uint4(prs[4], prs[5], prs[6], prs[7]);
        }

        // epilogue: shift + exp + rowsum + stage P (bf16 pairs, own-thread)
        #pragma unroll
        for (int mt = 0; mt < 2; mt++) {
            #pragma unroll
            for (int nt = 0; nt < 4; nt++) {
                int cl = wn * 32 + nt * 8 + q4 * 2;
                #pragma unroll
                for (int rr = 0; rr < 2; rr++) {
                    int rl = wm * 32 + mt * 16 + g + rr * 8;
                    int i = i0 + rl, j = j0 + cl;
                    float sh0 = shift_val(BDb, i, j);
                    float sh1 = shift_val(BDb, i, j + 1);
                    float e0 = __expf((acc[mt][nt][rr * 2 + 0] + sh0) * 0.125f);
                    float e1 = __expf((acc[mt][nt][rr * 2 + 1] + sh1) * 0.125f);
                    rs[mt][rr] += e0 + e1;
                    __nv_bfloat162 pr = __floats2bfloat162_rn(e0, e1);
                    Ps[rl][cl >> 1] = *reinterpret_cast<uint32_t*>(&pr);
                }
            }
        }
        __syncthreads(); // P and V visible

        // P@V MMA: k = 64 j-values = 32 pairs
        #pragma unroll
        for (int kc = 0; kc < 4; kc++) {
            int kb = kc * 8;
            uint32_t af[2][4];
            #pragma unroll
            for (int mt = 0; mt < 2; mt++) {
                int r = wm * 32 + mt * 16 + g;
                af[mt][0] = Ps[r][kb + q4];      af[mt][1] = Ps[r + 8][kb + q4];
                af[mt][2] = Ps[r][kb + q4 + 4];  af[mt][3] = Ps[r + 8][kb + q4 + 4];
            }
            #pragma unroll
            for (int nt = 0; nt < 4; nt++) {
                int c = wn * 32 + nt * 8 + g;
                uint32_t bf[2];
                bf[0] = Vs[c][kb + q4]; bf[1] = Vs[c][kb + q4 + 4];
                mma16bf(o_acc[0][nt], af[0], bf);
                mma16bf(o_acc[1][nt], af[1], bf);
            }
        }
    }

    // final row sums: quad shfl -> cross-warp(wn) smem combine
    #pragma unroll
    for (int mt = 0; mt < 2; mt++) {
        #pragma unroll
        for (int rr = 0; rr < 2; rr++) {
            float s = rs[mt][rr];
            s += __shfl_xor_sync(0xffffffffu, s, 1);
            s += __shfl_xor_sync(0xffffffffu, s, 2);
            int r = wm * 32 + mt * 16 + g + rr * 8;
            if (q4 == 0) redS[wn * 128 + r] = s;
        }
    }
    __syncthreads();

    float* Cg = ctx + ((size_t)(b * T + i0)) * D + h * HD;
    #pragma unroll
    for (int mt = 0; mt < 2; mt++) {
        #pragma unroll
        for (int rr = 0; rr < 2; rr++) {
            int r = wm * 32 + mt * 16 + g + rr * 8;
            float inv = 1.0f / (redS[r] + redS[128 + r]);
            #pragma unroll
            for (int nt = 0; nt < 4; nt++) {
                int c = wn * 32 + nt * 8 + q4 * 2;
                *reinterpret_cast<float2*>(Cg + (size_t)r * D + c) =
                    make_float2(o_acc[mt][nt][rr * 2 + 0] * inv,
                                o_acc[mt][nt][rr * 2 + 1] * inv);
            }
        }
    }
}

// ---------------- launch -----------------------------------------------------
extern "C" void kernel_launch(void* const* d_in, const int* in_sizes, int n_in,
                              void* d_out, int out_size) {
    const float* inputs = (const float*)d_in[0];
    const float* pos    = (const float*)d_in[1];
    const float* gamma  = (const float*)d_in[2];
    const float* beta   = (const float*)d_in[3];
    const float* wq     = (const float*)d_in[4];
    const float* bq     = (const float*)d_in[5];
    const float* wk     = (const float*)d_in[6];
    const float* bk     = (const float*)d_in[7];
    const float* wv     = (const float*)d_in[8];
    const float* bv     = (const float*)d_in[9];
    const float* wpos   = (const float*)d_in[10];
    const float* u      = (const float*)d_in[11];
    const float* vb     = (const float*)d_in[12];
    const float* wo     = (const float*)d_in[13];
    const float* bo     = (const float*)d_in[14];
    float* out = (float*)d_out;

    float *xn, *qu, *qv, *kx, *vx, *px, *ctx, *bd;
    cudaGetSymbolAddress((void**)&xn,  g_xn);
    cudaGetSymbolAddress((void**)&qu,  g_qu);
    cudaGetSymbolAddress((void**)&qv,  g_qv);
    cudaGetSymbolAddress((void**)&kx,  g_k);
    cudaGetSymbolAddress((void**)&vx,  g_v);
    cudaGetSymbolAddress((void**)&px,  g_p);
    cudaGetSymbolAddress((void**)&ctx, g_ctx);
    cudaGetSymbolAddress((void**)&bd,  g_bd);

    const int SGEMM_SMEM = SGEMM_SMEM_U32 * 4; // 71680
    const int SCORE_SMEM = 2 * 128 * 68 * 4;
    const int FUSED_SMEM = FUSED_SMEM_U32 * 4; // 98304
    cudaFuncSetAttribute(sgemm512_tf32, cudaFuncAttributeMaxDynamicSharedMemorySize, SGEMM_SMEM);
    cudaFuncSetAttribute(score_tf32, cudaFuncAttributeMaxDynamicSharedMemorySize, SCORE_SMEM);
    cudaFuncSetAttribute(fused_softmax_av, cudaFuncAttributeMaxDynamicSharedMemorySize, FUSED_SMEM);

    // 1. LayerNorm
    ln_kernel<<<M, 128>>>(inputs, gamma, beta, xn);

    // 2. Projections (tf32 MMA, 2-stage cp.async)
    dim3 gg(4, 64);
    sgemm512_tf32<<<gg, 256, SGEMM_SMEM>>>(xn,  wq,   bq,      u,       nullptr, qu, vb, qv);
    sgemm512_tf32<<<gg, 256, SGEMM_SMEM>>>(xn,  wk,   bk,      nullptr, nullptr, kx, nullptr, nullptr);
    sgemm512_tf32<<<gg, 256, SGEMM_SMEM>>>(xn,  wv,   bv,      nullptr, nullptr, vx, nullptr, nullptr);
    sgemm512_tf32<<<gg, 256, SGEMM_SMEM>>>(pos, wpos, nullptr, nullptr, nullptr, px, nullptr, nullptr);

    // 3. BD = (Qv) @ P^T (fp32)
    dim3 sg(8, NB * H);
    score_tf32<<<sg, 256, SCORE_SMEM>>>(qv, px, bd);

    // 4. fused content + shift + exp + P@V -> ctx
    fused_softmax_av<<<dim3(8, NB * H), 256, FUSED_SMEM>>>(qu, kx, vx, bd, ctx);

    // 5. output projection + bias + residual
    sgemm512_tf32<<<gg, 256, SGEMM_SMEM>>>(ctx, wo, bo, nullptr, inputs, out, nullptr, nullptr);
}

// round 16
// speedup vs baseline: 1.2550x; 1.0644x over previous
#include <cuda_runtime.h>
#include <cuda_bf16.h>
#include <cstdint>

// Problem constants
constexpr int NB = 8;      // batch
constexpr int T  = 1024;   // sequence
constexpr int D  = 512;    // model dim
constexpr int H  = 8;      // heads
constexpr int HD = 64;     // head dim
constexpr int M  = NB * T; // 8192 rows

// ---------------- scratch (device globals; allocation-free at runtime) -------
__device__ float g_xn[M * D];
__device__ float g_qu[M * D];
__device__ float g_qv[M * D];
__device__ float g_k [M * D];
__device__ float g_v [M * D];
__device__ float g_p [M * D];
__device__ float g_ctx[M * D];
__device__ float g_bd[(size_t)NB * H * T * T]; // pre-shift pos scores (fp32)

// ---------------- helpers ----------------------------------------------------
__device__ __forceinline__ void mma8(float* c, const uint32_t* a, const uint32_t* b) {
    asm volatile(
        "mma.sync.aligned.m16n8k8.row.col.f32.tf32.tf32.f32 "
        "{%0,%1,%2,%3}, {%4,%5,%6,%7}, {%8,%9}, {%0,%1,%2,%3};\n"
        : "+f"(c[0]), "+f"(c[1]), "+f"(c[2]), "+f"(c[3])
        : "r"(a[0]), "r"(a[1]), "r"(a[2]), "r"(a[3]), "r"(b[0]), "r"(b[1]));
}
__device__ __forceinline__ void mma16bf(float* c, const uint32_t* a, const uint32_t* b) {
    asm volatile(
        "mma.sync.aligned.m16n8k16.row.col.f32.bf16.bf16.f32 "
        "{%0,%1,%2,%3}, {%4,%5,%6,%7}, {%8,%9}, {%0,%1,%2,%3};\n"
        : "+f"(c[0]), "+f"(c[1]), "+f"(c[2]), "+f"(c[3])
        : "r"(a[0]), "r"(a[1]), "r"(a[2]), "r"(a[3]), "r"(b[0]), "r"(b[1]));
}
__device__ __forceinline__ void cpa16(uint32_t dst, const void* src) {
    asm volatile("cp.async.cg.shared.global [%0], [%1], 16;" :: "r"(dst), "l"(src));
}

// rel_shift lookup (fp32 source)
__device__ __forceinline__ float shift_val(const float* __restrict__ BDb, int i, int j) {
    if (j <= i)      return BDb[(size_t)i * T + (j - i + T - 1)];
    if (j == i + 1)  return 0.f;
    return BDb[(size_t)(i + 1) * T + (j - i - 2)];
}

// ---------------- LayerNorm --------------------------------------------------
__global__ void ln_kernel(const float* __restrict__ x,
                          const float* __restrict__ gamma,
                          const float* __restrict__ beta,
                          float* __restrict__ out) {
    int row = blockIdx.x;
    int t = threadIdx.x; // 128 threads
    const float4* xr = reinterpret_cast<const float4*>(x + (size_t)row * D);
    float4 v = xr[t];
    float s = v.x + v.y + v.z + v.w;
    __shared__ float red[4], red2[4];
    #pragma unroll
    for (int o = 16; o > 0; o >>= 1) s += __shfl_xor_sync(0xffffffffu, s, o);
    if ((t & 31) == 0) red[t >> 5] = s;
    __syncthreads();
    float mu = (red[0] + red[1] + red[2] + red[3]) * (1.0f / D);
    float dx = v.x - mu, dy = v.y - mu, dz = v.z - mu, dw = v.w - mu;
    float ss = dx * dx + dy * dy + dz * dz + dw * dw;
    #pragma unroll
    for (int o = 16; o > 0; o >>= 1) ss += __shfl_xor_sync(0xffffffffu, ss, o);
    if ((t & 31) == 0) red2[t >> 5] = ss;
    __syncthreads();
    float var = (red2[0] + red2[1] + red2[2] + red2[3]) * (1.0f / D);
    float rstd = rsqrtf(var + 1e-3f);
    const float4* g4 = reinterpret_cast<const float4*>(gamma);
    const float4* b4 = reinterpret_cast<const float4*>(beta);
    float4 g = g4[t], b = b4[t];
    float4 o4;
    o4.x = dx * rstd * g.x + b.x;
    o4.y = dy * rstd * g.y + b.y;
    o4.z = dz * rstd * g.z + b.z;
    o4.w = dw * rstd * g.w + b.w;
    reinterpret_cast<float4*>(out + (size_t)row * D)[t] = o4;
}

// ---------------- GEMM core (shared by proj_all and sgemm512) ----------------
constexpr int SG_A = 128 * 36;
constexpr int SG_B = 32 * 136;
constexpr int SGEMM_SMEM_U32 = 2 * SG_A + 2 * SG_B; // 71680 B

__device__ __forceinline__ void gemm_body(
    const float* __restrict__ A, const float* __restrict__ W,
    const float* __restrict__ bias, const float* __restrict__ biasU,
    const float* __restrict__ resid, float* __restrict__ out1,
    const float* __restrict__ biasV, float* __restrict__ out2,
    uint32_t* sg4, int bm, int bn) {
    int t = threadIdx.x;
    int wid = t >> 5, lane = t & 31;
    int wm = wid & 3, wn = wid >> 2;
    int g = lane >> 2, q4 = lane & 3;
    uint32_t sbase = (uint32_t)__cvta_generic_to_shared(sg4);

    float acc[2][8][4];
    #pragma unroll
    for (int i = 0; i < 2; i++)
        #pragma unroll
        for (int j = 0; j < 8; j++)
            #pragma unroll
            for (int k = 0; k < 4; k++) acc[i][j][k] = 0.f;

    auto load_stage = [&](int st, int k0) {
        #pragma unroll
        for (int p = 0; p < 4; p++) {
            int chunk = t + p * 256;
            int row = chunk >> 3, c4 = (chunk & 7) * 4;
            uint32_t dst = sbase + (uint32_t)(st * SG_A + row * 36 + c4) * 4u;
            cpa16(dst, A + (size_t)(bm + row) * D + k0 + c4);
        }
        #pragma unroll
        for (int p = 0; p < 4; p++) {
            int chunk = t + p * 256;
            int row = chunk >> 5, c4 = (chunk & 31) * 4;
            uint32_t dst = sbase + (uint32_t)(2 * SG_A + st * SG_B + row * 136 + c4) * 4u;
            cpa16(dst, W + (size_t)(k0 + row) * D + bn + c4);
        }
        asm volatile("cp.async.commit_group;");
    };

    load_stage(0, 0);

    for (int kt = 0; kt < 16; kt++) {
        __syncthreads();
        if (kt + 1 < 16) {
            load_stage((kt + 1) & 1, (kt + 1) * 32);
            asm volatile("cp.async.wait_group 1;");
        } else {
            asm volatile("cp.async.wait_group 0;");
        }
        __syncthreads();

        const uint32_t* Asb = sg4 + (kt & 1) * SG_A;
        const uint32_t* Bsb = sg4 + 2 * SG_A + (kt & 1) * SG_B;
        #pragma unroll
        for (int kc = 0; kc < 4; kc++) {
            int kb = kc * 8;
            uint32_t af[2][4];
            #pragma unroll
            for (int mt = 0; mt < 2; mt++) {
                int r = wm * 32 + mt * 16 + g;
                af[mt][0] = Asb[r * 36 + kb + q4];
                af[mt][1] = Asb[(r + 8) * 36 + kb + q4];
                af[mt][2] = Asb[r * 36 + kb + q4 + 4];
                af[mt][3] = Asb[(r + 8) * 36 + kb + q4 + 4];
            }
            #pragma unroll
            for (int nt = 0; nt < 8; nt++) {
                int c = wn * 64 + nt * 8 + g;
                uint32_t bf[2];
                bf[0] = Bsb[(kb + q4) * 136 + c];
                bf[1] = Bsb[(kb + q4 + 4) * 136 + c];
                mma8(acc[0][nt], af[0], bf);
                mma8(acc[1][nt], af[1], bf);
            }
        }
    }

    #pragma unroll
    for (int mt = 0; mt < 2; mt++) {
        int r0 = bm + wm * 32 + mt * 16 + g;
        #pragma unroll
        for (int nt = 0; nt < 8; nt++) {
            int c0 = bn + wn * 64 + nt * 8 + q4 * 2;
            #pragma unroll
            for (int rr = 0; rr < 2; rr++) {
                int r = r0 + rr * 8;
                float b0 = acc[mt][nt][rr * 2 + 0];
                float b1 = acc[mt][nt][rr * 2 + 1];
                if (bias) { b0 += bias[c0]; b1 += bias[c0 + 1]; }
                float v0 = b0, v1 = b1;
                if (biasU) { v0 += biasU[c0]; v1 += biasU[c0 + 1]; }
                if (resid) {
                    float2 rv = *reinterpret_cast<const float2*>(resid + (size_t)r * D + c0);
                    v0 += rv.x; v1 += rv.y;
                }
                *reinterpret_cast<float2*>(out1 + (size_t)r * D + c0) = make_float2(v0, v1);
                if (out2) {
                    float w0 = b0 + biasV[c0], w1 = b1 + biasV[c0 + 1];
                    *reinterpret_cast<float2*>(out2 + (size_t)r * D + c0) = make_float2(w0, w1);
                }
            }
        }
    }
}

// merged Q/K/V/P projections: blockIdx.z selects the operation
__global__ void __launch_bounds__(256, 2) proj_all(
    const float* __restrict__ xn, const float* __restrict__ pos,
    const float* __restrict__ wq, const float* __restrict__ wk,
    const float* __restrict__ wv, const float* __restrict__ wpos,
    const float* __restrict__ bq, const float* __restrict__ bk,
    const float* __restrict__ bv, const float* __restrict__ u,
    const float* __restrict__ vb,
    float* __restrict__ qu, float* __restrict__ qv, float* __restrict__ kx,
    float* __restrict__ vx, float* __restrict__ px) {
    extern __shared__ uint32_t sg4[];
    int op = blockIdx.z;
    const float* A = (op == 3) ? pos : xn;
    const float* W = (op == 0) ? wq : (op == 1) ? wk : (op == 2) ? wv : wpos;
    const float* bias  = (op == 0) ? bq : (op == 1) ? bk : (op == 2) ? bv : nullptr;
    const float* biasU = (op == 0) ? u  : nullptr;
    const float* biasV = (op == 0) ? vb : nullptr;
    float* out1 = (op == 0) ? qu : (op == 1) ? kx : (op == 2) ? vx : px;
    float* out2 = (op == 0) ? qv : nullptr;
    gemm_body(A, W, bias, biasU, nullptr, out1, biasV, out2,
              sg4, blockIdx.y * 128, blockIdx.x * 128);
}

// single GEMM (output projection with residual)
__global__ void __launch_bounds__(256, 2) sgemm512_tf32(
    const float* __restrict__ A, const float* __restrict__ W,
    const float* __restrict__ bias, const float* __restrict__ resid,
    float* __restrict__ out1) {
    extern __shared__ uint32_t sg4[];
    gemm_body(A, W, bias, nullptr, resid, out1, nullptr, nullptr,
              sg4, blockIdx.y * 128, blockIdx.x * 128);
}

// ------- score GEMM (BD): cp.async pipelined, raw fp32-as-tf32 ---------------
constexpr int SC_Q = 128 * 68;
constexpr int SC_K = 128 * 68;
constexpr int SCORE_SMEM_U32 = SC_Q + 2 * SC_K; // 26112 u32 = 104448 B

__global__ void __launch_bounds__(256, 2) score_tf32(
    const float* __restrict__ Qx, const float* __restrict__ Kx, float* __restrict__ S) {
    extern __shared__ uint32_t sm4[];
    uint32_t (*Qs)[68] = reinterpret_cast<uint32_t(*)[68]>(sm4);
    uint32_t sbase = (uint32_t)__cvta_generic_to_shared(sm4);
    int bh = blockIdx.y;
    int b = bh >> 3, h = bh & 7;
    int i0 = blockIdx.x * 128;
    const float* Qb = Qx + (size_t)b * T * D + h * HD;
    const float* Kb = Kx + (size_t)b * T * D + h * HD;
    int t = threadIdx.x, wid = t >> 5, lane = t & 31;
    int wm = wid & 3, wn = wid >> 2;
    int g = lane >> 2, q4 = lane & 3;

    auto load_k = [&](int st, int j0) {
        #pragma unroll
        for (int p = 0; p < 8; p++) {
            int chunk = t + p * 256;
            int row = chunk >> 4, c4 = (chunk & 15) * 4;
            uint32_t dst = sbase + (uint32_t)(SC_Q + st * SC_K + row * 68 + c4) * 4u;
            cpa16(dst, Kb + (size_t)(j0 + row) * D + c4);
        }
        asm volatile("cp.async.commit_group;");
    };

    // Q tile via cp.async (raw fp32)
    #pragma unroll
    for (int p = 0; p < 8; p++) {
        int chunk = t + p * 256;
        int row = chunk >> 4, c4 = (chunk & 15) * 4;
        uint32_t dst = sbase + (uint32_t)(row * 68 + c4) * 4u;
        cpa16(dst, Qb + (size_t)(i0 + row) * D + c4);
    }
    load_k(0, 0);

    for (int it = 0; it < 8; it++) {
        int j0 = it * 128;
        asm volatile("cp.async.wait_group 0;");
        __syncthreads(); // K stage it resident; iter it-1 reads complete

        if (it + 1 < 8) load_k((it + 1) & 1, j0 + 128);

        const uint32_t* Ksb = sm4 + SC_Q + (it & 1) * SC_K;

        float acc[2][8][4];
        #pragma unroll
        for (int i = 0; i < 2; i++)
            #pragma unroll
            for (int j = 0; j < 8; j++)
                #pragma unroll
                for (int k = 0; k < 4; k++) acc[i][j][k] = 0.f;

        #pragma unroll
        for (int kc = 0; kc < 8; kc++) {
            int kb = kc * 8;
            uint32_t af[2][4];
            #pragma unroll
            for (int mt = 0; mt < 2; mt++) {
                int r = wm * 32 + mt * 16 + g;
                af[mt][0] = Qs[r][kb + q4];      af[mt][1] = Qs[r + 8][kb + q4];
                af[mt][2] = Qs[r][kb + q4 + 4];  af[mt][3] = Qs[r + 8][kb + q4 + 4];
            }
            #pragma unroll
            for (int nt = 0; nt < 8; nt++) {
                int c = wn * 64 + nt * 8 + g;
                uint32_t bf[2];
                bf[0] = Ksb[c * 68 + kb + q4]; bf[1] = Ksb[c * 68 + kb + q4 + 4];
                mma8(acc[0][nt], af[0], bf);
                mma8(acc[1][nt], af[1], bf);
            }
        }

        #pragma unroll
        for (int mt = 0; mt < 2; mt++) {
            int r0 = i0 + wm * 32 + mt * 16 + g;
            #pragma unroll
            for (int nt = 0; nt < 8; nt++) {
                int c0 = j0 + wn * 64 + nt * 8 + q4 * 2;
                size_t base = ((size_t)bh * T + r0) * T + c0;
                *reinterpret_cast<float2*>(S + base) =
                    make_float2(acc[mt][nt][0], acc[mt][nt][1]);
                *reinterpret_cast<float2*>(S + base + (size_t)8 * T) =
                    make_float2(acc[mt][nt][2], acc[mt][nt][3]);
            }
        }
    }
}

// ======= fused: content + shift + exp + P@V (R15 proven) =====================
constexpr int FQ_OFF = 0;
constexpr int FK_OFF = FQ_OFF + 128 * 68;
constexpr int FK_ST  = 64 * 68;
constexpr int FV_OFF = FK_OFF + 2 * FK_ST;
constexpr int FP_OFF = FV_OFF + 64 * 36;
constexpr int FR_OFF = FP_OFF + 128 * 36;
constexpr int FUSED_SMEM_U32 = FR_OFF + 256; // 98304 B

__global__ void __launch_bounds__(256, 2) fused_softmax_av(
    const float* __restrict__ Qx, const float* __restrict__ Kx,
    const float* __restrict__ Vx, const float* __restrict__ BD,
    float* __restrict__ ctx) {
    extern __shared__ uint32_t sm4[];
    uint32_t (*Qs)[68] = reinterpret_cast<uint32_t(*)[68]>(sm4 + FQ_OFF);
    uint32_t (*Vs)[36] = reinterpret_cast<uint32_t(*)[36]>(sm4 + FV_OFF);
    uint32_t (*Ps)[36] = reinterpret_cast<uint32_t(*)[36]>(sm4 + FP_OFF);
    float* redS = reinterpret_cast<float*>(sm4 + FR_OFF);
    uint32_t sbase = (uint32_t)__cvta_generic_to_shared(sm4);

    int bh = blockIdx.y;
    int b = bh >> 3, h = bh & 7;
    int i0 = blockIdx.x * 128;
    const float* Qb = Qx + (size_t)b * T * D + h * HD;
    const float* Kb = Kx + (size_t)b * T * D + h * HD;
    const float* Vb = Vx + (size_t)b * T * D + h * HD;
    const float* BDb = BD + (size_t)bh * T * T;

    int t = threadIdx.x, wid = t >> 5, lane = t & 31;
    int wm = wid & 3, wn = wid >> 2;
    int g = lane >> 2, q4 = lane & 3;

    auto load_k = [&](int st, int j0) {
        #pragma unroll
        for (int p = 0; p < 4; p++) {
            int chunk = t + p * 256;
            int row = chunk >> 4, c4 = (chunk & 15) * 4;
            uint32_t dst = sbase + (uint32_t)(FK_OFF + st * FK_ST + row * 68 + c4) * 4u;
            cpa16(dst, Kb + (size_t)(j0 + row) * D + c4);
        }
        asm volatile("cp.async.commit_group;");
    };

    #pragma unroll
    for (int p = 0; p < 8; p++) {
        int chunk = t + p * 256;
        int row = chunk >> 4, c4 = (chunk & 15) * 4;
        uint32_t dst = sbase + (uint32_t)(FQ_OFF + row * 68 + c4) * 4u;
        cpa16(dst, Qb + (size_t)(i0 + row) * D + c4);
    }
    load_k(0, 0);

    float rs[2][2] = {{0.f, 0.f}, {0.f, 0.f}};
    float o_acc[2][4][4];
    #pragma unroll
    for (int i = 0; i < 2; i++)
        #pragma unroll
        for (int j = 0; j < 4; j++)
            #pragma unroll
            for (int k = 0; k < 4; k++) o_acc[i][j][k] = 0.f;

    int vcol = t & 63, vg = t >> 6;

    for (int it = 0; it < 16; it++) {
        int j0 = it * 64;
        asm volatile("cp.async.wait_group 0;");
        __syncthreads();

        if (it + 1 < 16) load_k((it + 1) & 1, j0 + 64);

        float vl[8], vh[8];
        #pragma unroll
        for (int kk = 0; kk < 8; kk++) {
            int kp = vg * 8 + kk;
            vl[kk] = Vb[(size_t)(j0 + 2 * kp) * D + vcol];
            vh[kk] = Vb[(size_t)(j0 + 2 * kp + 1) * D + vcol];
        }

        const uint32_t* Ksb = sm4 + FK_OFF + (it & 1) * FK_ST;

        float acc[2][4][4];
        #pragma unroll
        for (int i = 0; i < 2; i++)
            #pragma unroll
            for (int j = 0; j < 4; j++)
                #pragma unroll
                for (int k = 0; k < 4; k++) acc[i][j][k] = 0.f;
        #pragma unroll
        for (int kc = 0; kc < 8; kc++) {
            int kb = kc * 8;
            uint32_t af[2][4];
            #pragma unroll
            for (int mt = 0; mt < 2; mt++) {
                int r = wm * 32 + mt * 16 + g;
                af[mt][0] = Qs[r][kb + q4];      af[mt][1] = Qs[r + 8][kb + q4];
                af[mt][2] = Qs[r][kb + q4 + 4];  af[mt][3] = Qs[r + 8][kb + q4 + 4];
            }
            #pragma unroll
            for (int nt = 0; nt < 4; nt++) {
                int c = wn * 32 + nt * 8 + g;
                uint32_t bf[2];
                bf[0] = Ksb[c * 68 + kb + q4]; bf[1] = Ksb[c * 68 + kb + q4 + 4];
                mma8(acc[0][nt], af[0], bf);
                mma8(acc[1][nt], af[1], bf);
            }
        }

        {
            uint32_t prs[8];
            #pragma unroll
            for (int kk = 0; kk < 8; kk++) {
                __nv_bfloat162 pr = __floats2bfloat162_rn(vl[kk], vh[kk]);
                prs[kk] = *reinterpret_cast<uint32_t*>(&pr);
            }
            *reinterpret_cast<uint4*>(&Vs[vcol][vg * 8 + 0]) =
                make_uint4(prs[0], prs[1], prs[2], prs[3]);
            *reinterpret_cast<uint4*>(&Vs[vcol][vg * 8 + 4]) =
                make_uint4(prs[4], prs[5], prs[6], prs[7]);
        }

        #pragma unroll
        for (int mt = 0; mt < 2; mt++) {
            #pragma unroll
            for (int nt = 0; nt < 4; nt++) {
                int cl = wn * 32 + nt * 8 + q4 * 2;
                #pragma unroll
                for (int rr = 0; rr < 2; rr++) {
                    int rl = wm * 32 + mt * 16 + g + rr * 8;
                    int i = i0 + rl, j = j0 + cl;
                    float sh0 = shift_val(BDb, i, j);
                    float sh1 = shift_val(BDb, i, j + 1);
                    float e0 = __expf((acc[mt][nt][rr * 2 + 0] + sh0) * 0.125f);
                    float e1 = __expf((acc[mt][nt][rr * 2 + 1] + sh1) * 0.125f);
                    rs[mt][rr] += e0 + e1;
                    __nv_bfloat162 pr = __floats2bfloat162_rn(e0, e1);
                    Ps[rl][cl >> 1] = *reinterpret_cast<uint32_t*>(&pr);
                }
            }
        }
        __syncthreads();

        #pragma unroll
        for (int kc = 0; kc < 4; kc++) {
            int kb = kc * 8;
            uint32_t af[2][4];
            #pragma unroll
            for (int mt = 0; mt < 2; mt++) {
                int r = wm * 32 + mt * 16 + g;
                af[mt][0] = Ps[r][kb + q4];      af[mt][1] = Ps[r + 8][kb + q4];
                af[mt][2] = Ps[r][kb + q4 + 4];  af[mt][3] = Ps[r + 8][kb + q4 + 4];
            }
            #pragma unroll
            for (int nt = 0; nt < 4; nt++) {
                int c = wn * 32 + nt * 8 + g;
                uint32_t bf[2];
                bf[0] = Vs[c][kb + q4]; bf[1] = Vs[c][kb + q4 + 4];
                mma16bf(o_acc[0][nt], af[0], bf);
                mma16bf(o_acc[1][nt], af[1], bf);
            }
        }
    }

    #pragma unroll
    for (int mt = 0; mt < 2; mt++) {
        #pragma unroll
        for (int rr = 0; rr < 2; rr++) {
            float s = rs[mt][rr];
            s += __shfl_xor_sync(0xffffffffu, s, 1);
            s += __shfl_xor_sync(0xffffffffu, s, 2);
            int r = wm * 32 + mt * 16 + g + rr * 8;
            if (q4 == 0) redS[wn * 128 + r] = s;
        }
    }
    __syncthreads();

    float* Cg = ctx + ((size_t)(b * T + i0)) * D + h * HD;
    #pragma unroll
    for (int mt = 0; mt < 2; mt++) {
        #pragma unroll
        for (int rr = 0; rr < 2; rr++) {
            int r = wm * 32 + mt * 16 + g + rr * 8;
            float inv = 1.0f / (redS[r] + redS[128 + r]);
            #pragma unroll
            for (int nt = 0; nt < 4; nt++) {
                int c = wn * 32 + nt * 8 + q4 * 2;
                *reinterpret_cast<float2*>(Cg + (size_t)r * D + c) =
                    make_float2(o_acc[mt][nt][rr * 2 + 0] * inv,
                                o_acc[mt][nt][rr * 2 + 1] * inv);
            }
        }
    }
}

// ---------------- launch -----------------------------------------------------
extern "C" void kernel_launch(void* const* d_in, const int* in_sizes, int n_in,
                              void* d_out, int out_size) {
    const float* inputs = (const float*)d_in[0];
    const float* pos    = (const float*)d_in[1];
    const float* gamma  = (const float*)d_in[2];
    const float* beta   = (const float*)d_in[3];
    const float* wq     = (const float*)d_in[4];
    const float* bq     = (const float*)d_in[5];
    const float* wk     = (const float*)d_in[6];
    const float* bk     = (const float*)d_in[7];
    const float* wv     = (const float*)d_in[8];
    const float* bv     = (const float*)d_in[9];
    const float* wpos   = (const float*)d_in[10];
    const float* u      = (const float*)d_in[11];
    const float* vb     = (const float*)d_in[12];
    const float* wo     = (const float*)d_in[13];
    const float* bo     = (const float*)d_in[14];
    float* out = (float*)d_out;

    float *xn, *qu, *qv, *kx, *vx, *px, *ctx, *bd;
    cudaGetSymbolAddress((void**)&xn,  g_xn);
    cudaGetSymbolAddress((void**)&qu,  g_qu);
    cudaGetSymbolAddress((void**)&qv,  g_qv);
    cudaGetSymbolAddress((void**)&kx,  g_k);
    cudaGetSymbolAddress((void**)&vx,  g_v);
    cudaGetSymbolAddress((void**)&px,  g_p);
    cudaGetSymbolAddress((void**)&ctx, g_ctx);
    cudaGetSymbolAddress((void**)&bd,  g_bd);

    const int SGEMM_SMEM = SGEMM_SMEM_U32 * 4; // 71680
    const int SCORE_SMEM = SCORE_SMEM_U32 * 4; // 104448
    const int FUSED_SMEM = FUSED_SMEM_U32 * 4; // 98304
    cudaFuncSetAttribute(proj_all, cudaFuncAttributeMaxDynamicSharedMemorySize, SGEMM_SMEM);
    cudaFuncSetAttribute(sgemm512_tf32, cudaFuncAttributeMaxDynamicSharedMemorySize, SGEMM_SMEM);
    cudaFuncSetAttribute(score_tf32, cudaFuncAttributeMaxDynamicSharedMemorySize, SCORE_SMEM);
    cudaFuncSetAttribute(fused_softmax_av, cudaFuncAttributeMaxDynamicSharedMemorySize, FUSED_SMEM);

    // 1. LayerNorm
    ln_kernel<<<M, 128>>>(inputs, gamma, beta, xn);

    // 2. All four projections in one launch (z selects op)
    proj_all<<<dim3(4, 64, 4), 256, SGEMM_SMEM>>>(
        xn, pos, wq, wk, wv, wpos, bq, bk, bv, u, vb, qu, qv, kx, vx, px);

    // 3. BD = (Qv) @ P^T (fp32, pipelined)
    score_tf32<<<dim3(8, NB * H), 256, SCORE_SMEM>>>(qv, px, bd);

    // 4. fused content + shift + exp + P@V -> ctx
    fused_softmax_av<<<dim3(8, NB * H), 256, FUSED_SMEM>>>(qu, kx, vx, bd, ctx);

    // 5. output projection + bias + residual
    sgemm512_tf32<<<dim3(4, 64), 256, SGEMM_SMEM>>>(ctx, wo, bo, inputs, out);
}